// round 2
// baseline (speedup 1.0000x reference)
#include <cuda_runtime.h>

#define B_ 32
#define L_ 4096
#define H_ 1024

// Scratch: projected hidden v[b,h] = sum_g hid[b,g] * W[g,h]
__device__ float g_v[B_ * H_];

// ---------------------------------------------------------------------------
// Kernel A: v = hid @ W   (tiny: 32x1024 outputs, dot length 1024)
// Consecutive threads -> consecutive h, so W[g, h..h+255] loads coalesce.
// W (4 MB) is streamed from DRAM once; the other 31 b-values hit L2.
// ---------------------------------------------------------------------------
__global__ void proj_hidden(const float* __restrict__ hid,
                            const float* __restrict__ W) {
    const int h = blockIdx.x * blockDim.x + threadIdx.x;
    const int b = blockIdx.y;
    const float* __restrict__ hrow = hid + b * H_;
    float acc = 0.f;
#pragma unroll 8
    for (int g = 0; g < H_; ++g)
        acc = fmaf(hrow[g], W[g * H_ + h], acc);
    g_v[b * H_ + h] = acc;
}

// ---------------------------------------------------------------------------
// Kernel B: energies[b,l] = v[b] . enc[l,b,:]
// One warp per 8 consecutive l of one b. Each lane keeps its 32 v-floats
// (8 x float4) in registers, loaded once and reused across the 8 rows, so v
// contributes no per-row L2 traffic. enc rows are contiguous 4 KB -> float4
// coalesced. Writes raw energies into d_out (softmax'd in place next).
// ---------------------------------------------------------------------------
__global__ void energies_kernel(const float* __restrict__ enc,
                                float* __restrict__ out) {
    const int b    = blockIdx.y;
    const int warp = threadIdx.x >> 5;
    const int lane = threadIdx.x & 31;

    const float4* __restrict__ v4 = (const float4*)(g_v + b * H_);
    float4 v[8];
#pragma unroll
    for (int i = 0; i < 8; ++i) v[i] = v4[i * 32 + lane];

    const int l0 = (blockIdx.x * 8 + warp) * 8;  // 8 l per warp
    // Base pointer for first row; advance by row stride B_*H_ each j.
    const float4* __restrict__ e4 =
        (const float4*)(enc + ((size_t)l0 * B_ + b) * (size_t)H_);
    const size_t row_stride4 = (size_t)B_ * H_ / 4;   // in float4 units

#pragma unroll
    for (int j = 0; j < 8; ++j) {
        float s = 0.f;
#pragma unroll
        for (int i = 0; i < 8; ++i) {
            float4 e = e4[i * 32 + lane];
            s = fmaf(v[i].x, e.x, s);
            s = fmaf(v[i].y, e.y, s);
            s = fmaf(v[i].z, e.z, s);
            s = fmaf(v[i].w, e.w, s);
        }
#pragma unroll
        for (int o = 16; o; o >>= 1)
            s += __shfl_down_sync(0xffffffffu, s, o);
        if (lane == 0) out[b * L_ + l0 + j] = s;
        e4 += row_stride4;
    }
}

// ---------------------------------------------------------------------------
// Kernel C: in-place softmax over l for each b. One block per b.
// Note: the per-row constant hid[b].bias cancels in softmax, so bias is
// never read at all.
// ---------------------------------------------------------------------------
__global__ void softmax_kernel(float* __restrict__ out) {
    __shared__ float sdata[L_];   // 16 KB
    __shared__ float red[32];
    const int b   = blockIdx.x;
    const int tid = threadIdx.x;          // 256 threads
    float* __restrict__ row = out + b * L_;

    // --- max ---
    float m = -1e30f;
    for (int i = tid; i < L_; i += 256) {
        float x = row[i];
        sdata[i] = x;
        m = fmaxf(m, x);
    }
#pragma unroll
    for (int o = 16; o; o >>= 1) m = fmaxf(m, __shfl_xor_sync(0xffffffffu, m, o));
    if ((tid & 31) == 0) red[tid >> 5] = m;
    __syncthreads();
    if (tid < 32) {
        float t = (tid < 8) ? red[tid] : -1e30f;
#pragma unroll
        for (int o = 4; o; o >>= 1) t = fmaxf(t, __shfl_xor_sync(0xffffffffu, t, o));
        red[tid] = t;
    }
    __syncthreads();
    m = red[0];
    __syncthreads();

    // --- exp + sum ---
    float s = 0.f;
    for (int i = tid; i < L_; i += 256) {
        float e = __expf(sdata[i] - m);
        sdata[i] = e;
        s += e;
    }
#pragma unroll
    for (int o = 16; o; o >>= 1) s += __shfl_xor_sync(0xffffffffu, s, o);
    if ((tid & 31) == 0) red[tid >> 5] = s;
    __syncthreads();
    if (tid < 32) {
        float t = (tid < 8) ? red[tid] : 0.f;
#pragma unroll
        for (int o = 4; o; o >>= 1) t += __shfl_xor_sync(0xffffffffu, t, o);
        red[tid] = t;
    }
    __syncthreads();
    const float inv = 1.f / red[0];

    // --- normalize ---
    for (int i = tid; i < L_; i += 256) row[i] = sdata[i] * inv;
}

// ---------------------------------------------------------------------------
extern "C" void kernel_launch(void* const* d_in, const int* in_sizes, int n_in,
                              void* d_out, int out_size) {
    const float* hid = (const float*)d_in[0];   // [1,B,H]
    const float* enc = (const float*)d_in[1];   // [L,B,H]
    const float* W   = (const float*)d_in[2];   // [H,H]
    // d_in[3] = bias: provably irrelevant (softmax shift invariance)
    float* out = (float*)d_out;                 // [B,1,L]

    proj_hidden   <<<dim3(H_ / 256, B_), 256>>>(hid, W);
    energies_kernel<<<dim3(L_ / 64, B_), 256>>>(enc, out);
    softmax_kernel<<<B_, 256>>>(out);
}

// round 3
// speedup vs baseline: 1.4710x; 1.4710x over previous
#include <cuda_runtime.h>

#define B_ 32
#define L_ 4096
#define H_ 1024

#define GSPLIT 32                 // g-chunks for split-K projection
#define GCH    (H_ / GSPLIT)      // 32 g per chunk

// Scratch: split-K partials + final projected hidden v[b,h]
__device__ float g_vp[GSPLIT * B_ * H_];   // 4 MB
__device__ float g_v[B_ * H_];

// ---------------------------------------------------------------------------
// Kernel A1: split-K partial projection.
//   vp[gc, b, h] = sum_{g in chunk gc} hid[b,g] * W[g,h]
// Grid (H/128, GSPLIT) = 256 blocks x 128 threads. Each thread owns one h and
// 32 independent per-b accumulators (full ILP, no serial FMA chain). W[g,h]
// is loaded once per (g,h) and reused across all 32 b. hid chunk sits in smem.
// ---------------------------------------------------------------------------
__global__ void proj_partial(const float* __restrict__ hid,
                             const float* __restrict__ W) {
    const int h  = blockIdx.x * 128 + threadIdx.x;
    const int gc = blockIdx.y;

    __shared__ float sh[B_][GCH];           // 4 KB: hid[b, gc*GCH + g]
    for (int i = threadIdx.x; i < B_ * GCH; i += 128) {
        const int b = i / GCH, g = i % GCH;
        sh[b][g] = hid[b * H_ + gc * GCH + g];
    }
    __syncthreads();

    float acc[B_];
#pragma unroll
    for (int b = 0; b < B_; ++b) acc[b] = 0.f;

    const float* __restrict__ Wp = W + (size_t)(gc * GCH) * H_ + h;
#pragma unroll
    for (int g = 0; g < GCH; ++g) {
        const float w = Wp[(size_t)g * H_];   // coalesced across threads
#pragma unroll
        for (int b = 0; b < B_; ++b)
            acc[b] = fmaf(sh[b][g], w, acc[b]);
    }

    float* __restrict__ outp = g_vp + (size_t)gc * (B_ * H_) + h;
#pragma unroll
    for (int b = 0; b < B_; ++b) outp[(size_t)b * H_] = acc[b];
}

// ---------------------------------------------------------------------------
// Kernel A2: reduce partials. v[i] = sum_gc vp[gc, i], i over B*H.
// Partials are L2-hot (4 MB just written). 128 blocks x 256 threads.
// ---------------------------------------------------------------------------
__global__ void proj_reduce() {
    const int i = blockIdx.x * 256 + threadIdx.x;   // 0 .. B*H-1
    float s = 0.f;
#pragma unroll
    for (int c = 0; c < GSPLIT; ++c)
        s += g_vp[(size_t)c * (B_ * H_) + i];
    g_v[i] = s;
}

// ---------------------------------------------------------------------------
// Kernel B: energies[b,l] = v[b] . enc[l,b,:]
// One warp per 8 consecutive l of one b. Each lane keeps its 32 v-floats
// (8 x float4) in registers, reused across the 8 rows -> v adds ~no L2
// traffic. enc rows are contiguous 4 KB -> float4 coalesced. This kernel is
// the 512 MiB DRAM streamer and should sit at the LTS ceiling.
// ---------------------------------------------------------------------------
__global__ void energies_kernel(const float* __restrict__ enc,
                                float* __restrict__ out) {
    const int b    = blockIdx.y;
    const int warp = threadIdx.x >> 5;
    const int lane = threadIdx.x & 31;

    const float4* __restrict__ v4 = (const float4*)(g_v + b * H_);
    float4 v[8];
#pragma unroll
    for (int i = 0; i < 8; ++i) v[i] = v4[i * 32 + lane];

    const int l0 = (blockIdx.x * 8 + warp) * 8;  // 8 l per warp
    const float4* __restrict__ e4 =
        (const float4*)(enc + ((size_t)l0 * B_ + b) * (size_t)H_);
    const size_t row_stride4 = (size_t)B_ * H_ / 4;

#pragma unroll
    for (int j = 0; j < 8; ++j) {
        float s = 0.f;
#pragma unroll
        for (int i = 0; i < 8; ++i) {
            float4 e = e4[i * 32 + lane];
            s = fmaf(v[i].x, e.x, s);
            s = fmaf(v[i].y, e.y, s);
            s = fmaf(v[i].z, e.z, s);
            s = fmaf(v[i].w, e.w, s);
        }
#pragma unroll
        for (int o = 16; o; o >>= 1)
            s += __shfl_down_sync(0xffffffffu, s, o);
        if (lane == 0) out[b * L_ + l0 + j] = s;
        e4 += row_stride4;
    }
}

// ---------------------------------------------------------------------------
// Kernel C: in-place softmax over l for each b. One block per b.
// hid[b].bias is a per-row constant -> cancels in softmax; bias never read.
// ---------------------------------------------------------------------------
__global__ void softmax_kernel(float* __restrict__ out) {
    __shared__ float sdata[L_];   // 16 KB
    __shared__ float red[32];
    const int b   = blockIdx.x;
    const int tid = threadIdx.x;          // 256 threads
    float* __restrict__ row = out + b * L_;

    float m = -1e30f;
    for (int i = tid; i < L_; i += 256) {
        float x = row[i];
        sdata[i] = x;
        m = fmaxf(m, x);
    }
#pragma unroll
    for (int o = 16; o; o >>= 1) m = fmaxf(m, __shfl_xor_sync(0xffffffffu, m, o));
    if ((tid & 31) == 0) red[tid >> 5] = m;
    __syncthreads();
    if (tid < 32) {
        float t = (tid < 8) ? red[tid] : -1e30f;
#pragma unroll
        for (int o = 4; o; o >>= 1) t = fmaxf(t, __shfl_xor_sync(0xffffffffu, t, o));
        red[tid] = t;
    }
    __syncthreads();
    m = red[0];
    __syncthreads();

    float s = 0.f;
    for (int i = tid; i < L_; i += 256) {
        float e = __expf(sdata[i] - m);
        sdata[i] = e;
        s += e;
    }
#pragma unroll
    for (int o = 16; o; o >>= 1) s += __shfl_xor_sync(0xffffffffu, s, o);
    if ((tid & 31) == 0) red[tid >> 5] = s;
    __syncthreads();
    if (tid < 32) {
        float t = (tid < 8) ? red[tid] : 0.f;
#pragma unroll
        for (int o = 4; o; o >>= 1) t += __shfl_xor_sync(0xffffffffu, t, o);
        red[tid] = t;
    }
    __syncthreads();
    const float inv = 1.f / red[0];

    for (int i = tid; i < L_; i += 256) row[i] = sdata[i] * inv;
}

// ---------------------------------------------------------------------------
extern "C" void kernel_launch(void* const* d_in, const int* in_sizes, int n_in,
                              void* d_out, int out_size) {
    const float* hid = (const float*)d_in[0];   // [1,B,H]
    const float* enc = (const float*)d_in[1];   // [L,B,H]
    const float* W   = (const float*)d_in[2];   // [H,H]
    // d_in[3] = bias: irrelevant (softmax shift invariance)
    float* out = (float*)d_out;                 // [B,1,L]

    proj_partial  <<<dim3(H_ / 128, GSPLIT), 128>>>(hid, W);
    proj_reduce   <<<B_ * H_ / 256, 256>>>();
    energies_kernel<<<dim3(L_ / 64, B_), 256>>>(enc, out);
    softmax_kernel<<<B_, 256>>>(out);
}

// round 5
// speedup vs baseline: 1.6891x; 1.1483x over previous
#include <cuda_runtime.h>

#define B_ 32
#define L_ 4096
#define H_ 1024

#define GSPLIT 32                 // g-chunks for split-K projection
#define GCH    (H_ / GSPLIT)      // 32 g per chunk

// Scratch: split-K partials + final projected hidden v[b,h]
__device__ float g_vp[GSPLIT * B_ * H_];   // 4 MB
__device__ float g_v[B_ * H_];

// ---------------------------------------------------------------------------
// Kernel A1: split-K partial projection.
//   vp[gc, b, h] = sum_{g in chunk gc} hid[b,g] * W[g,h]
// ---------------------------------------------------------------------------
__global__ void proj_partial(const float* __restrict__ hid,
                             const float* __restrict__ W) {
    const int h  = blockIdx.x * 128 + threadIdx.x;
    const int gc = blockIdx.y;

    __shared__ float sh[B_][GCH];           // 4 KB: hid[b, gc*GCH + g]
    for (int i = threadIdx.x; i < B_ * GCH; i += 128) {
        const int b = i / GCH, g = i % GCH;
        sh[b][g] = hid[b * H_ + gc * GCH + g];
    }
    __syncthreads();

    float acc[B_];
#pragma unroll
    for (int b = 0; b < B_; ++b) acc[b] = 0.f;

    const float* __restrict__ Wp = W + (size_t)(gc * GCH) * H_ + h;
#pragma unroll
    for (int g = 0; g < GCH; ++g) {
        const float w = Wp[(size_t)g * H_];   // coalesced across threads
#pragma unroll
        for (int b = 0; b < B_; ++b)
            acc[b] = fmaf(sh[b][g], w, acc[b]);
    }

    float* __restrict__ outp = g_vp + (size_t)gc * (B_ * H_) + h;
#pragma unroll
    for (int b = 0; b < B_; ++b) outp[(size_t)b * H_] = acc[b];
}

// ---------------------------------------------------------------------------
// Kernel A2: reduce partials (L2-hot). v[i] = sum_gc vp[gc, i].
// ---------------------------------------------------------------------------
__global__ void proj_reduce() {
    const int i = blockIdx.x * 256 + threadIdx.x;   // 0 .. B*H-1
    float s = 0.f;
#pragma unroll
    for (int c = 0; c < GSPLIT; ++c)
        s += g_vp[(size_t)c * (B_ * H_) + i];
    g_v[i] = s;
}

// ---------------------------------------------------------------------------
// Kernel B: energies[b,l] = v[b] . enc[l,b,:]
// One warp per 8 consecutive l of one b. Lane-resident v (8 float4).
// Loop nest: outer over H-chunks i, inner over rows j with 8 per-thread
// partials -> mainloop is pure load+FMA, 8 independent loads in flight,
// no warp sync until the final reductions. 512 MiB DRAM streamer.
// ---------------------------------------------------------------------------
__global__ void energies_kernel(const float* __restrict__ enc,
                                float* __restrict__ out) {
    const int b    = blockIdx.y;
    const int warp = threadIdx.x >> 5;
    const int lane = threadIdx.x & 31;

    const float4* __restrict__ v4 = (const float4*)(g_v + b * H_);
    float4 v[8];
#pragma unroll
    for (int i = 0; i < 8; ++i) v[i] = v4[i * 32 + lane];

    const int l0 = (blockIdx.x * 8 + warp) * 8;  // 8 l per warp
    const float4* __restrict__ base =
        (const float4*)(enc + ((size_t)l0 * B_ + b) * (size_t)H_);
    const size_t row4 = (size_t)B_ * H_ / 4;     // row stride in float4

    float s[8];
#pragma unroll
    for (int j = 0; j < 8; ++j) s[j] = 0.f;

#pragma unroll
    for (int i = 0; i < 8; ++i) {
#pragma unroll
        for (int j = 0; j < 8; ++j) {
            float4 e = base[(size_t)j * row4 + i * 32 + lane];
            s[j] = fmaf(v[i].x, e.x, s[j]);
            s[j] = fmaf(v[i].y, e.y, s[j]);
            s[j] = fmaf(v[i].z, e.z, s[j]);
            s[j] = fmaf(v[i].w, e.w, s[j]);
        }
    }

#pragma unroll
    for (int j = 0; j < 8; ++j) {
        float t = s[j];
#pragma unroll
        for (int o = 16; o; o >>= 1)
            t += __shfl_down_sync(0xffffffffu, t, o);
        if (lane == 0) out[b * L_ + l0 + j] = t;
    }
}

// ---------------------------------------------------------------------------
// Kernel C: in-place softmax, one block of 1024 threads per b.
// One float4 per thread held in registers: load once, reduce twice, store.
// (bias cancels in softmax -> never read.)
// ---------------------------------------------------------------------------
__global__ void softmax_kernel(float* __restrict__ out) {
    __shared__ float red[32];
    const int tid  = threadIdx.x;          // 0..1023
    const int lane = tid & 31, wid = tid >> 5;
    float4* __restrict__ row4 = (float4*)(out + blockIdx.x * L_);

    float4 x = row4[tid];

    // --- max ---
    float m = fmaxf(fmaxf(x.x, x.y), fmaxf(x.z, x.w));
#pragma unroll
    for (int o = 16; o; o >>= 1) m = fmaxf(m, __shfl_xor_sync(0xffffffffu, m, o));
    if (lane == 0) red[wid] = m;
    __syncthreads();
    if (tid < 32) {
        float t = red[lane];
#pragma unroll
        for (int o = 16; o; o >>= 1) t = fmaxf(t, __shfl_xor_sync(0xffffffffu, t, o));
        red[lane] = t;
    }
    __syncthreads();
    m = red[0];

    // --- exp + sum ---
    x.x = __expf(x.x - m);
    x.y = __expf(x.y - m);
    x.z = __expf(x.z - m);
    x.w = __expf(x.w - m);
    float s = (x.x + x.y) + (x.z + x.w);
#pragma unroll
    for (int o = 16; o; o >>= 1) s += __shfl_xor_sync(0xffffffffu, s, o);
    __syncthreads();                        // red reuse
    if (lane == 0) red[wid] = s;
    __syncthreads();
    if (tid < 32) {
        float t = red[lane];
#pragma unroll
        for (int o = 16; o; o >>= 1) t += __shfl_xor_sync(0xffffffffu, t, o);
        red[lane] = t;
    }
    __syncthreads();
    const float inv = 1.f / red[0];

    x.x *= inv; x.y *= inv; x.z *= inv; x.w *= inv;
    row4[tid] = x;
}

// ---------------------------------------------------------------------------
extern "C" void kernel_launch(void* const* d_in, const int* in_sizes, int n_in,
                              void* d_out, int out_size) {
    const float* hid = (const float*)d_in[0];   // [1,B,H]
    const float* enc = (const float*)d_in[1];   // [L,B,H]
    const float* W   = (const float*)d_in[2];   // [H,H]
    // d_in[3] = bias: irrelevant (softmax shift invariance)
    float* out = (float*)d_out;                 // [B,1,L]

    proj_partial  <<<dim3(H_ / 128, GSPLIT), 128>>>(hid, W);
    proj_reduce   <<<B_ * H_ / 256, 256>>>();
    energies_kernel<<<dim3(L_ / 64, B_), 256>>>(enc, out);
    softmax_kernel<<<B_, 1024>>>(out);
}

// round 6
// speedup vs baseline: 1.7127x; 1.0140x over previous
#include <cuda_runtime.h>

#define B_ 32
#define L_ 4096
#define H_ 1024

#define GSPLIT 32                 // g-chunks for split-K projection
#define GCH    (H_ / GSPLIT)      // 32 g per chunk

// Scratch
__device__ float g_vp[GSPLIT * B_ * H_];   // 4 MB split-K partials
__device__ float g_v[B_ * H_];             // projected hidden
__device__ int   g_cnt[B_];                // arrival counters (zero-init,
                                           // self-resetting -> replay-safe)

// ---------------------------------------------------------------------------
// Kernel A1: split-K partial projection.
//   vp[gc, b, h] = sum_{g in chunk gc} hid[b,g] * W[g,h]
// 256 blocks x 128 thr; 32 independent per-b accumulators per thread.
// ---------------------------------------------------------------------------
__global__ void proj_partial(const float* __restrict__ hid,
                             const float* __restrict__ W) {
    const int h  = blockIdx.x * 128 + threadIdx.x;
    const int gc = blockIdx.y;

    __shared__ float sh[B_][GCH];           // 4 KB
    for (int i = threadIdx.x; i < B_ * GCH; i += 128) {
        const int b = i / GCH, g = i % GCH;
        sh[b][g] = hid[b * H_ + gc * GCH + g];
    }
    __syncthreads();

    float acc[B_];
#pragma unroll
    for (int b = 0; b < B_; ++b) acc[b] = 0.f;

    const float* __restrict__ Wp = W + (size_t)(gc * GCH) * H_ + h;
#pragma unroll
    for (int g = 0; g < GCH; ++g) {
        const float w = Wp[(size_t)g * H_];   // coalesced
#pragma unroll
        for (int b = 0; b < B_; ++b)
            acc[b] = fmaf(sh[b][g], w, acc[b]);
    }

    float* __restrict__ outp = g_vp + (size_t)gc * (B_ * H_) + h;
#pragma unroll
    for (int b = 0; b < B_; ++b) outp[(size_t)b * H_] = acc[b];
}

// ---------------------------------------------------------------------------
// Kernel A2: reduce partials (L2-hot). v[i] = sum_gc vp[gc, i].
// ---------------------------------------------------------------------------
__global__ void proj_reduce() {
    const int i = blockIdx.x * 256 + threadIdx.x;   // 0 .. B*H-1
    float s = 0.f;
#pragma unroll
    for (int c = 0; c < GSPLIT; ++c)
        s += g_vp[(size_t)c * (B_ * H_) + i];
    g_v[i] = s;
}

// ---------------------------------------------------------------------------
// Kernel B: energies + fused softmax epilogue.
// 512 threads, 16 warps x 4 rows = 64 rows/block; 64 blocks per b.
// v[b] lives in smem (4 KB, conflict-free float4 reads) -> ~40 regs/thread
// -> 3-4 CTAs/SM for deep load pipelining on the 512 MiB enc stream.
// The LAST block to finish for a given b (global arrival counter) softmaxes
// that row in place while its energies are still L2-hot.
// ---------------------------------------------------------------------------
__global__ void energies_softmax(const float* __restrict__ enc,
                                 float* __restrict__ out) {
    const int b    = blockIdx.y;
    const int tid  = threadIdx.x;
    const int warp = tid >> 5;
    const int lane = tid & 31;

    __shared__ float4 sv[H_ / 4];   // 4 KB: v[b]
    __shared__ float  red[16];
    __shared__ int    s_last;

    {
        const float4* __restrict__ v4 = (const float4*)(g_v + b * H_);
        for (int i = tid; i < H_ / 4; i += 512) sv[i] = v4[i];
    }
    __syncthreads();

    const int l0 = (blockIdx.x * 16 + warp) * 4;     // 4 rows per warp
    const float4* __restrict__ base =
        (const float4*)(enc + ((size_t)l0 * B_ + b) * (size_t)H_);
    const size_t row4 = (size_t)B_ * H_ / 4;

    float s[4] = {0.f, 0.f, 0.f, 0.f};
#pragma unroll
    for (int i = 0; i < 8; ++i) {
        const float4 vv = sv[i * 32 + lane];
#pragma unroll
        for (int j = 0; j < 4; ++j) {
            float4 e = base[(size_t)j * row4 + i * 32 + lane];
            s[j] = fmaf(vv.x, e.x, s[j]);
            s[j] = fmaf(vv.y, e.y, s[j]);
            s[j] = fmaf(vv.z, e.z, s[j]);
            s[j] = fmaf(vv.w, e.w, s[j]);
        }
    }

#pragma unroll
    for (int j = 0; j < 4; ++j) {
        float t = s[j];
#pragma unroll
        for (int o = 16; o; o >>= 1)
            t += __shfl_down_sync(0xffffffffu, t, o);
        if (lane == 0) out[b * L_ + l0 + j] = t;
    }

    // ---- arrival: is this the last block for row b? ----
    __threadfence();                 // make energy writes device-visible
    __syncthreads();
    if (tid == 0) {
        const int old = atomicAdd(&g_cnt[b], 1);
        s_last = (old == gridDim.x - 1);
    }
    __syncthreads();
    if (!s_last) return;

    // ---- softmax epilogue on L2-hot row (one block per b) ----
    float4* __restrict__ o4 = (float4*)(out + b * L_);   // 1024 float4
    float4 x0 = o4[tid];
    float4 x1 = o4[tid + 512];

    float m = fmaxf(fmaxf(fmaxf(x0.x, x0.y), fmaxf(x0.z, x0.w)),
                    fmaxf(fmaxf(x1.x, x1.y), fmaxf(x1.z, x1.w)));
#pragma unroll
    for (int o = 16; o; o >>= 1) m = fmaxf(m, __shfl_xor_sync(0xffffffffu, m, o));
    if (lane == 0) red[warp] = m;
    __syncthreads();
    if (tid < 32) {
        float t = (lane < 16) ? red[lane] : -1e30f;
#pragma unroll
        for (int o = 8; o; o >>= 1) t = fmaxf(t, __shfl_xor_sync(0xffffffffu, t, o));
        red[lane & 15] = t;
    }
    __syncthreads();
    m = red[0];

    x0.x = __expf(x0.x - m); x0.y = __expf(x0.y - m);
    x0.z = __expf(x0.z - m); x0.w = __expf(x0.w - m);
    x1.x = __expf(x1.x - m); x1.y = __expf(x1.y - m);
    x1.z = __expf(x1.z - m); x1.w = __expf(x1.w - m);
    float sum = ((x0.x + x0.y) + (x0.z + x0.w)) +
                ((x1.x + x1.y) + (x1.z + x1.w));
#pragma unroll
    for (int o = 16; o; o >>= 1) sum += __shfl_xor_sync(0xffffffffu, sum, o);
    __syncthreads();
    if (lane == 0) red[warp] = sum;
    __syncthreads();
    if (tid < 32) {
        float t = (lane < 16) ? red[lane] : 0.f;
#pragma unroll
        for (int o = 8; o; o >>= 1) t += __shfl_xor_sync(0xffffffffu, t, o);
        red[lane & 15] = t;
    }
    __syncthreads();
    const float inv = 1.f / red[0];

    x0.x *= inv; x0.y *= inv; x0.z *= inv; x0.w *= inv;
    x1.x *= inv; x1.y *= inv; x1.z *= inv; x1.w *= inv;
    o4[tid]       = x0;
    o4[tid + 512] = x1;

    if (tid == 0) g_cnt[b] = 0;      // self-reset for next replay
}

// ---------------------------------------------------------------------------
extern "C" void kernel_launch(void* const* d_in, const int* in_sizes, int n_in,
                              void* d_out, int out_size) {
    const float* hid = (const float*)d_in[0];   // [1,B,H]
    const float* enc = (const float*)d_in[1];   // [L,B,H]
    const float* W   = (const float*)d_in[2];   // [H,H]
    // d_in[3] = bias: irrelevant (softmax shift invariance)
    float* out = (float*)d_out;                 // [B,1,L]

    proj_partial    <<<dim3(H_ / 128, GSPLIT), 128>>>(hid, W);
    proj_reduce     <<<B_ * H_ / 256, 256>>>();
    energies_softmax<<<dim3(L_ / 64, B_), 512>>>(enc, out);
}